// round 5
// baseline (speedup 1.0000x reference)
#include <cuda_runtime.h>

#define BATCH 256
#define TT    2048
#define FEAT  10
#define HID   64
#define GATES 192   // 3*HID

typedef unsigned long long ull;

__device__ __forceinline__ ull ffma2(ull a, ull b, ull c) {
    ull d;
    asm("fma.rn.f32x2 %0, %1, %2, %3;" : "=l"(d) : "l"(a), "l"(b), "l"(c));
    return d;
}
__device__ __forceinline__ ull fadd2(ull a, ull b) {
    ull d;
    asm("add.rn.f32x2 %0, %1, %2;" : "=l"(d) : "l"(a), "l"(b));
    return d;
}
__device__ __forceinline__ ull pack2(float lo, float hi) {
    ull r;
    asm("mov.b64 %0, {%1, %2};" : "=l"(r) : "f"(lo), "f"(hi));
    return r;
}
__device__ __forceinline__ float2 unpack2(ull a) {
    float lo, hi;
    asm("mov.b64 {%0, %1}, %2;" : "=f"(lo), "=f"(hi) : "l"(a));
    return make_float2(lo, hi);
}

// sigmoid via hardware EX2/RCP (~1e-7 rel err)
__device__ __forceinline__ float sigmoid_f(float x) {
    return __fdividef(1.0f, 1.0f + __expf(-x));
}
// tanh(x) = 2/(1+exp(-2x)) - 1 ; saturates correctly for large |x|
__device__ __forceinline__ float tanh_f(float x) {
    return fmaf(2.0f, __fdividef(1.0f, 1.0f + __expf(-2.0f * x)), -1.0f);
}

extern "C" __global__ void __launch_bounds__(GATES, 2)
gru_kernel(const float* __restrict__ noise,
           const float* __restrict__ w_ih,
           const float* __restrict__ w_hh,
           const float* __restrict__ b_ih,
           const float* __restrict__ b_hh,
           float* __restrict__ out)
{
    extern __shared__ float smem[];
    float* s_noise = smem;                   // TT*FEAT = 20480 floats (80 KB)
    float* s_h     = smem + TT * FEAT;       // 64 floats (16B aligned)
    float* s_rz    = s_h + HID;              // 128 floats: r[0:64], z[64:128]
    float* s_gn    = s_rz + 2 * HID;         // 64 floats: g_n
    float* s_dn    = s_gn + HID;             // 64 floats: h@w_hn^T + b_hn

    const int o = threadIdx.x;               // gate-output row 0..191
    const int b = blockIdx.x;                // batch element

    // ---- Preload this batch element's entire noise stream into shared ----
    {
        const float4* g4 = (const float4*)(noise + (size_t)b * TT * FEAT);
        float4* s4 = (float4*)s_noise;
        #pragma unroll 4
        for (int i = o; i < (TT * FEAT) / 4; i += GATES) s4[i] = g4[i];
    }
    if (o < HID) s_h[o] = 0.0f;

    // ---- Recurrent weights for row o: 64 floats packed into 32 b64 regs ----
    ull wp[32];
    {
        const float4* w4 = (const float4*)(w_hh + o * HID);
        #pragma unroll
        for (int i = 0; i < 16; i++) {
            float4 w = w4[i];
            wp[2 * i]     = pack2(w.x, w.y);
            wp[2 * i + 1] = pack2(w.z, w.w);
        }
    }
    // Input-projection weights, packed in pairs (FEAT=10 -> 5 pairs)
    ull wip[FEAT / 2];
    #pragma unroll
    for (int i = 0; i < FEAT / 2; i++)
        wip[i] = pack2(w_ih[o * FEAT + 2 * i], w_ih[o * FEAT + 2 * i + 1]);

    const float bi = b_ih[o];
    const float bh = b_hh[o];
    // r/z rows: fold b_ih + b_hh into one bias. n row: b_hh must stay inside
    // the r*(...) term.
    const float gi_bias = (o < 2 * HID) ? (bi + bh) : bi;

    // Epilogue assignment spread over all 6 warps / 4 SMSPs:
    // thread o with o%3==0 handles element j=o/3 (j in 0..63).
    const bool epi = (o % 3 == 0);
    const int  j   = o / 3;

    __syncthreads();

    // input projection for t=0 (packed pairs; noise row offset 40B, 8B aligned)
    float gi;
    {
        const ull* np2 = (const ull*)s_noise;
        ull acc = pack2(gi_bias, 0.0f);
        #pragma unroll
        for (int i = 0; i < FEAT / 2; i++) acc = ffma2(wip[i], np2[i], acc);
        float2 f = unpack2(acc);
        gi = f.x + f.y;
    }

    float* outb = out + (size_t)b * TT * HID;

    for (int t = 0; t < TT; t++) {
        // ---- recurrent matvec row: dot(h, w_hh[o,:]) via packed f32x2 FMA ----
        ull a0 = 0ull, a1 = 0ull, a2 = 0ull, a3 = 0ull;
        const ulonglong2* h2 = (const ulonglong2*)s_h;
        #pragma unroll
        for (int i = 0; i < 16; i += 2) {
            ulonglong2 hv0 = h2[i];       // LDS.128 broadcast (4 h values)
            ulonglong2 hv1 = h2[i + 1];
            a0 = ffma2(wp[2 * i],     hv0.x, a0);
            a1 = ffma2(wp[2 * i + 1], hv0.y, a1);
            a2 = ffma2(wp[2 * i + 2], hv1.x, a2);
            a3 = ffma2(wp[2 * i + 3], hv1.y, a3);
        }
        ull s = fadd2(fadd2(a0, a1), fadd2(a2, a3));
        float2 f = unpack2(s);
        float dot = f.x + f.y;

        if (o < 2 * HID) {
            // r/z: apply sigmoid HERE, in parallel across 128 threads,
            // before the barrier — off the serial chain.
            s_rz[o] = sigmoid_f(gi + dot);
        } else {
            s_gn[o - 2 * HID] = gi;              // g_n (with b_ih_n)
            s_dn[o - 2 * HID] = dot + bh;        // h@w_hn^T + b_hn
        }
        __syncthreads();

        // Overlap: next step's input projection (independent of h)
        if (t + 1 < TT) {
            const ull* np2 = (const ull*)(s_noise + (t + 1) * FEAT);
            ull acc = pack2(gi_bias, 0.0f);
            #pragma unroll
            for (int i = 0; i < FEAT / 2; i++) acc = ffma2(wip[i], np2[i], acc);
            float2 g = unpack2(acc);
            gi = g.x + g.y;
        }

        // ---- epilogue: 64 threads spread across all warps ----
        if (epi) {
            float r  = s_rz[j];
            float z  = s_rz[HID + j];
            float n  = tanh_f(fmaf(r, s_dn[j], s_gn[j]));
            float h  = fmaf(z, s_h[j] - n, n);   // (1-z)*n + z*h_old
            s_h[j] = h;
            outb[(size_t)t * HID + j] = h;       // fire-and-forget
        }
        __syncthreads();
    }
}

extern "C" void kernel_launch(void* const* d_in, const int* in_sizes, int n_in,
                              void* d_out, int out_size)
{
    const float* noise = (const float*)d_in[0];
    const float* w_ih  = (const float*)d_in[1];
    const float* w_hh  = (const float*)d_in[2];
    const float* b_ih  = (const float*)d_in[3];
    const float* b_hh  = (const float*)d_in[4];
    float* out = (float*)d_out;

    const size_t smem_bytes =
        (size_t)(TT * FEAT + HID + 2 * HID + HID + HID) * sizeof(float); // 83968 B

    cudaFuncSetAttribute(gru_kernel,
                         cudaFuncAttributeMaxDynamicSharedMemorySize,
                         (int)smem_bytes);

    gru_kernel<<<BATCH, GATES, smem_bytes>>>(noise, w_ih, w_hh, b_ih, b_hh, out);
}

// round 7
// speedup vs baseline: 1.4332x; 1.4332x over previous
#include <cuda_runtime.h>

#define BATCH 256
#define TT    2048
#define FEAT  10
#define HID   64

typedef unsigned long long ull;

__device__ __forceinline__ ull ffma2(ull a, ull b, ull c) {
    ull d;
    asm("fma.rn.f32x2 %0, %1, %2, %3;" : "=l"(d) : "l"(a), "l"(b), "l"(c));
    return d;
}
__device__ __forceinline__ ull fadd2(ull a, ull b) {
    ull d;
    asm("add.rn.f32x2 %0, %1, %2;" : "=l"(d) : "l"(a), "l"(b));
    return d;
}
__device__ __forceinline__ ull pack2(float lo, float hi) {
    ull r;
    asm("mov.b64 %0, {%1, %2};" : "=l"(r) : "f"(lo), "f"(hi));
    return r;
}
__device__ __forceinline__ float2 unpack2(ull a) {
    float lo, hi;
    asm("mov.b64 {%0, %1}, %2;" : "=f"(lo), "=f"(hi) : "l"(a));
    return make_float2(lo, hi);
}

// sigmoid via hardware EX2/RCP (~1e-7 rel err)
__device__ __forceinline__ float sigmoid_f(float x) {
    return __fdividef(1.0f, 1.0f + __expf(-x));
}
// tanh(x) = 2/(1+exp(-2x)) - 1 ; saturates correctly for large |x|
__device__ __forceinline__ float tanh_f(float x) {
    return fmaf(2.0f, __fdividef(1.0f, 1.0f + __expf(-2.0f * x)), -1.0f);
}

extern "C" __global__ void __launch_bounds__(128, 2)
gru_kernel(const float* __restrict__ noise,
           const float* __restrict__ w_ih,
           const float* __restrict__ w_hh,
           const float* __restrict__ b_ih,
           const float* __restrict__ b_hh,
           float* __restrict__ out)
{
    extern __shared__ float smem[];
    float* s_noise = smem;                 // TT*FEAT = 20480 floats (80 KB)
    float* s_h     = smem + TT * FEAT;     // 2 x 64 floats, ping-pong

    const int tid  = threadIdx.x;
    const int b    = blockIdx.x;
    const int l    = tid & 31;
    const int w    = tid >> 5;
    const int e    = (w << 4) | (l & 15);  // hidden element owned by this lane pair
    const int half = l >> 4;               // K-half: 0 -> h[0:32], 1 -> h[32:64]

    // ---- Preload this batch element's entire noise stream into shared ----
    {
        const float4* g4 = (const float4*)(noise + (size_t)b * TT * FEAT);
        float4* s4 = (float4*)s_noise;
        #pragma unroll 4
        for (int i = tid; i < (TT * FEAT) / 4; i += 128) s4[i] = g4[i];
    }
    s_h[tid >> 0] = 0.0f;  // tid in [0,128): zeros both ping-pong buffers

    // ---- Recurrent weights: this lane's K-half of rows e, 64+e, 128+e ----
    // Chunk rotation: half1 accesses chunk (i+2)&7 while half0 accesses chunk i,
    // so the two broadcast groups in one LDS.128 never collide on banks.
    ull wr[16], wz[16], wn[16];
    int coff[8];                            // h word offsets (include half*32)
    #pragma unroll
    for (int i = 0; i < 8; i++) {
        int c   = (i + 2 * half) & 7;
        int col = half * 32 + 4 * c;
        coff[i] = col;
        float4 a = *(const float4*)(w_hh + (size_t)e * HID + col);
        wr[2 * i] = pack2(a.x, a.y); wr[2 * i + 1] = pack2(a.z, a.w);
        float4 bzv = *(const float4*)(w_hh + (size_t)(64 + e) * HID + col);
        wz[2 * i] = pack2(bzv.x, bzv.y); wz[2 * i + 1] = pack2(bzv.z, bzv.w);
        float4 bnv = *(const float4*)(w_hh + (size_t)(128 + e) * HID + col);
        wn[2 * i] = pack2(bnv.x, bnv.y); wn[2 * i + 1] = pack2(bnv.z, bnv.w);
    }

    // Input-projection weights: this lane's 5-feature half of rows e, 64+e, 128+e
    float wir[5], wiz[5], win[5];
    #pragma unroll
    for (int k = 0; k < 5; k++) {
        wir[k] = w_ih[(size_t)e         * FEAT + half * 5 + k];
        wiz[k] = w_ih[(size_t)(64 + e)  * FEAT + half * 5 + k];
        win[k] = w_ih[(size_t)(128 + e) * FEAT + half * 5 + k];
    }

    // Biases: added exactly once (half0 only). n-gate: b_hh_n stays inside r*(.)
    float bias_r = 0.f, bias_z = 0.f, bias_dn = 0.f, bias_gn = 0.f;
    if (half == 0) {
        bias_r  = b_ih[e]      + b_hh[e];
        bias_z  = b_ih[64 + e] + b_hh[64 + e];
        bias_dn = b_hh[128 + e];
        bias_gn = b_ih[128 + e];
    }

    __syncthreads();

    float h_prev = 0.0f;
    float* outb = out + (size_t)b * TT * HID;

    for (int t = 0; t < TT; t++) {
        const float* hb = s_h + (t & 1) * HID;          // read buffer
        const float* np = s_noise + t * FEAT + half * 5;

        // input-projection partials (this lane's 5 features)
        float x0 = np[0], x1 = np[1], x2 = np[2], x3 = np[3], x4 = np[4];
        float pr  = bias_r, pz = bias_z, pgn = bias_gn;
        pr = fmaf(x0, wir[0], pr); pr = fmaf(x1, wir[1], pr);
        pr = fmaf(x2, wir[2], pr); pr = fmaf(x3, wir[3], pr);
        pr = fmaf(x4, wir[4], pr);
        pz = fmaf(x0, wiz[0], pz); pz = fmaf(x1, wiz[1], pz);
        pz = fmaf(x2, wiz[2], pz); pz = fmaf(x3, wiz[3], pz);
        pz = fmaf(x4, wiz[4], pz);
        pgn = fmaf(x0, win[0], pgn); pgn = fmaf(x1, win[1], pgn);
        pgn = fmaf(x2, win[2], pgn); pgn = fmaf(x3, win[3], pgn);
        pgn = fmaf(x4, win[4], pgn);

        // recurrent half-dots for r, z, n (packed f32x2)
        ull ar0 = 0, ar1 = 0, az0 = 0, az1 = 0, an0 = 0, an1 = 0;
        #pragma unroll
        for (int i = 0; i < 8; i++) {
            ulonglong2 hv = *(const ulonglong2*)(hb + coff[i]);  // LDS.128 bcast
            ar0 = ffma2(wr[2 * i],     hv.x, ar0);
            ar1 = ffma2(wr[2 * i + 1], hv.y, ar1);
            az0 = ffma2(wz[2 * i],     hv.x, az0);
            az1 = ffma2(wz[2 * i + 1], hv.y, az1);
            an0 = ffma2(wn[2 * i],     hv.x, an0);
            an1 = ffma2(wn[2 * i + 1], hv.y, an1);
        }
        float2 f;
        f = unpack2(fadd2(ar0, ar1)); float sr  = pr + f.x + f.y;
        f = unpack2(fadd2(az0, az1)); float sz  = pz + f.x + f.y;
        f = unpack2(fadd2(an0, an1)); float sdn = bias_dn + f.x + f.y;
        float sgn = pgn;

        // combine the two K-halves (and split gi features) within the warp
        sr  += __shfl_xor_sync(0xffffffffu, sr,  16);
        sz  += __shfl_xor_sync(0xffffffffu, sz,  16);
        sdn += __shfl_xor_sync(0xffffffffu, sdn, 16);
        sgn += __shfl_xor_sync(0xffffffffu, sgn, 16);

        // epilogue (computed redundantly by both lanes of the pair — identical)
        float r = sigmoid_f(sr);
        float z = sigmoid_f(sz);
        float n = tanh_f(fmaf(r, sdn, sgn));
        float h = fmaf(z, h_prev - n, n);   // (1-z)*n + z*h_prev
        h_prev = h;

        if (l < 16) {
            s_h[((t & 1) ^ 1) * HID + e] = h;       // write ping-pong buffer
            outb[(size_t)t * HID + e] = h;          // fire-and-forget
        }
        __syncthreads();                            // the ONLY barrier per step
    }
}

extern "C" void kernel_launch(void* const* d_in, const int* in_sizes, int n_in,
                              void* d_out, int out_size)
{
    const float* noise = (const float*)d_in[0];
    const float* w_ih  = (const float*)d_in[1];
    const float* w_hh  = (const float*)d_in[2];
    const float* b_ih  = (const float*)d_in[3];
    const float* b_hh  = (const float*)d_in[4];
    float* out = (float*)d_out;

    const size_t smem_bytes = (size_t)(TT * FEAT + 2 * HID) * sizeof(float); // 82432 B

    cudaFuncSetAttribute(gru_kernel,
                         cudaFuncAttributeMaxDynamicSharedMemorySize,
                         (int)smem_bytes);

    gru_kernel<<<BATCH, 128, smem_bytes>>>(noise, w_ih, w_hh, b_ih, b_hh, out);
}